// round 13
// baseline (speedup 1.0000x reference)
#include <cuda_runtime.h>

// ---------------------------------------------------------------------------
// MogrifierRNN persistent kernel, round 12.  (base = round 11)
//   - NEW lane mapping: warp = 16 rows x 4 cols, thread = 2 rows x 1 col
//     => A reads dedup to 1 wavefront (8 distinct rows), W reads 1 wf
//   - weights stored TRANSPOSED (+pad) in per-warp smem slots, conflict-free
//   - gates fma-bound; mog crossbar cost halved
//   - everything else proven: 32x16 tile, direct-poll row barriers, cp.async
//     prefetch ring, FFMA2, register-resident c/h/xx, gates tile-reuse
// ---------------------------------------------------------------------------

#define S_LEN 512
#define B_DIM 128
#define HID   512
#define K_RANK 256
#define NQP   2

#define GRID_BLOCKS 128
#define NT          256
#define APITCH      516                 // conflict-free pitch (floats)
#define ABUF        (32 * APITCH)       // 16512 floats = 66,048 B
#define WSLOT_F     1088                // 4352 B slot (mog 260 f4 / gates 272 f4)
#define WWARP_F     (2 * WSLOT_F)
#define WRING_F     (8 * WWARP_F)       // 69,632 B
#define SMEM_FLOATS (2 * ABUF + WRING_F)        // 50432
#define SMEM_BYTES  (SMEM_FLOATS * 4)           // 201,728 B
#define BAR_STRIDE  32

typedef unsigned long long u64;

// ------------------------- device scratch ----------------------------------
__device__ float g_Q[NQP * HID * HID];   // Q[i][m][n]
__device__ float g_R[NQP * HID * HID];   // R[i][n][m]
__device__ float g_xx[B_DIM * HID];
__device__ float g_h[2][B_DIM * HID];
__device__ unsigned int g_arrive[GRID_BLOCKS * BAR_STRIDE];
__device__ unsigned int g_go_full;

__global__ void mg_init() {
    int i = (int)threadIdx.x;
    if (i < GRID_BLOCKS) g_arrive[i * BAR_STRIDE] = 0u;
    if (i == 0) g_go_full = 0u;
}

__device__ __forceinline__ float sigf(float v) {
    return 1.0f / (1.0f + __expf(-v));
}

// ---- packed fp32x2 FMA ------------------------------------------------------
union F4 { float4 f; ulonglong2 d; };

__device__ __forceinline__ void ffma2(u64& acc, u64 a, u64 b) {
    asm("fma.rn.f32x2 %0, %1, %2, %0;" : "+l"(acc) : "l"(a), "l"(b));
}
__device__ __forceinline__ float pairsum(u64 p) {
    return __uint_as_float((unsigned)p) + __uint_as_float((unsigned)(p >> 32));
}

// ---- cp.async ---------------------------------------------------------------
__device__ __forceinline__ void cpa16(float* dst_smem, const float* src) {
    unsigned d = (unsigned)__cvta_generic_to_shared(dst_smem);
    asm volatile("cp.async.cg.shared.global [%0], [%1], 16;"
                 :: "r"(d), "l"(src) : "memory");
}
__device__ __forceinline__ void cp_commit() {
    asm volatile("cp.async.commit_group;" ::: "memory");
}
template <int N> __device__ __forceinline__ void cp_waitg() {
    asm volatile("cp.async.wait_group %0;" :: "n"(N) : "memory");
}

// ---- barriers ---------------------------------------------------------------
__device__ __forceinline__ unsigned int ld_acq(const unsigned int* p) {
    unsigned int v;
    asm volatile("ld.acquire.gpu.global.u32 %0, [%1];"
                 : "=r"(v) : "l"(p) : "memory");
    return v;
}
__device__ __forceinline__ void st_rel(unsigned int* p, unsigned int v) {
    asm volatile("st.release.gpu.global.u32 [%0], %1;"
                 :: "l"(p), "r"(v) : "memory");
}

// Row-group barrier: the 32 blocks sharing rt (= blockIdx.x & 3). Direct-poll.
__device__ __forceinline__ void row_barrier(unsigned int& epoch, int rt) {
    epoch++;
    __syncthreads();
    if (threadIdx.x == 0) st_rel(&g_arrive[blockIdx.x * BAR_STRIDE], epoch);
    if (threadIdx.x < 32) {
        while (ld_acq(&g_arrive[(rt + 4 * threadIdx.x) * BAR_STRIDE]) < epoch) { }
    }
    __syncthreads();
}

// Full-grid barrier (once, after precompute).
__device__ __forceinline__ void full_barrier(unsigned int& epoch) {
    epoch++;
    __syncthreads();
    if (blockIdx.x == 0) {
        if (threadIdx.x == 0) st_rel(&g_arrive[0], epoch);
        if (threadIdx.x < GRID_BLOCKS) {
            while (ld_acq(&g_arrive[threadIdx.x * BAR_STRIDE]) < epoch) { }
        }
        __syncthreads();
        if (threadIdx.x == 0) st_rel(&g_go_full, epoch);
    } else {
        if (threadIdx.x == 0) {
            st_rel(&g_arrive[blockIdx.x * BAR_STRIDE], epoch);
            while (ld_acq(&g_go_full) < epoch) { }
        }
        __syncthreads();
    }
}

// ---- staging ----------------------------------------------------------------
// A k-half: rows [r0,r0+32) x k[256h,256h+256). One group.
__device__ __forceinline__ void stageA_half(float* As, const float* A,
                                            int r0, int half, int tid) {
#pragma unroll
    for (int i = 0; i < 8; i++) {
        int e = i * NT + tid;          // 0..2047 f4
        int row = e >> 6, q = e & 63;
        cpa16(As + row * APITCH + half * 256 + q * 4,
              A + (r0 + row) * HID + half * 256 + q * 4);
    }
    cp_commit();
}
// A full tile: one group.
__device__ __forceinline__ void stageA_full(float* As, const float* A,
                                            int r0, int tid) {
#pragma unroll
    for (int i = 0; i < 16; i++) {
        int e = i * NT + tid;
        int row = e >> 7, q = e & 127;
        cpa16(As + row * APITCH + q * 4, A + (r0 + row) * HID + q * 4);
    }
    cp_commit();
}

// Mog W prefetch: this warp's 4 cols, transposed. 2 groups (k halves).
// Slot s layout: f4 index = col*65 + kk, kk = local k4 (0..63), k = 256s+4kk.
__device__ __forceinline__ void mogw_issue(float* myW, const float* W,
                                           int jbase, int lane) {
#pragma unroll
    for (int s = 0; s < 2; s++) {
        float* slot = myW + s * WSLOT_F;
#pragma unroll
        for (int i = 0; i < 8; i++) {
            int f = lane + 32 * i;       // 0..255
            int col = f >> 6, kk = f & 63;
            cpa16(slot + (col * 65 + kk) * 4,
                  W + (jbase + col) * HID + s * 256 + kk * 4);
        }
        cp_commit();
    }
}

// Gates W chunk: 4 gates x 4 cols x 64 k, transposed. One group.
// Slot layout: f4 index = g*68 + col*17 + k4 (k4 0..15), k = kc + 4*k4.
__device__ __forceinline__ void gw_issue(float* slot, const float* Wsrc,
                                         int jbase, int kc, int lane) {
#pragma unroll
    for (int i = 0; i < 8; i++) {
        int f = lane + 32 * i;           // 0..255
        int k4 = f & 15, col = (f >> 4) & 3, g = f >> 6;
        cpa16(slot + (g * 68 + col * 17 + k4) * 4,
              Wsrc + (g * HID + jbase + col) * HID + kc + k4 * 4);
    }
    cp_commit();
}

// Mogrifier phase. Entering: this phase's W (2 groups) already issued.
// Thread computes rows {rArel, rArel+8} x col col_l (of its warp's 4).
__device__ __forceinline__ void mog_phase(float* As, float* myW,
                                          const float* Aglob, int r0,
                                          int rArel, int col_l, int tid,
                                          float mulA, float mulB,
                                          float& resA, float& resB) {
    stageA_half(As, Aglob, r0, 0, tid);
    stageA_half(As, Aglob, r0, 1, tid);

    u64 cAx = 0ull, cAy = 0ull, cBx = 0ull, cBy = 0ull;
    const float4* Ar0 = reinterpret_cast<const float4*>(As + rArel * APITCH);
    const float4* Ar1 = reinterpret_cast<const float4*>(As + (rArel + 8) * APITCH);

    cp_waitg<1>();                 // W0, W1, A-half0 done; A-half1 pending
    __syncthreads();
    {
        const float4* W4 = reinterpret_cast<const float4*>(myW);
#pragma unroll 16
        for (int kk = 0; kk < 64; kk++) {
            F4 a0, a1, w;
            a0.f = Ar0[kk];
            a1.f = Ar1[kk];
            w.f  = W4[col_l * 65 + kk];
            ffma2(cAx, a0.d.x, w.d.x); ffma2(cAy, a0.d.y, w.d.y);
            ffma2(cBx, a1.d.x, w.d.x); ffma2(cBy, a1.d.y, w.d.y);
        }
    }
    cp_waitg<0>();                 // A-half1 done
    __syncthreads();
    {
        const float4* W4 = reinterpret_cast<const float4*>(myW + WSLOT_F);
#pragma unroll 16
        for (int kk = 0; kk < 64; kk++) {
            F4 a0, a1, w;
            a0.f = Ar0[64 + kk];
            a1.f = Ar1[64 + kk];
            w.f  = W4[col_l * 65 + kk];
            ffma2(cAx, a0.d.x, w.d.x); ffma2(cAy, a0.d.y, w.d.y);
            ffma2(cBx, a1.d.x, w.d.x); ffma2(cBy, a1.d.y, w.d.y);
        }
    }
    resA = 2.0f * sigf(pairsum(cAx) + pairsum(cAy)) * mulA;
    resB = 2.0f * sigf(pairsum(cBx) + pairsum(cBy)) * mulB;
}

// One-time precompute of Q = QL@QR, R = RL@RR; zero h0.
__device__ void precompute(const float* QL, const float* QR,
                           const float* RL, const float* RR) {
    const int tid = (int)blockIdx.x * NT + (int)threadIdx.x;
    const int stride = GRID_BLOCKS * NT;
    for (int e = tid; e < NQP * HID * HID; e += stride) {
        int i = e >> 18;
        int rem = e & ((1 << 18) - 1);
        int m = rem >> 9, n = rem & 511;
        const float* L  = QL + i * HID * K_RANK + m * K_RANK;
        const float* Rp = QR + i * K_RANK * HID + n;
        float acc = 0.f;
#pragma unroll 8
        for (int k = 0; k < K_RANK; k++) acc = fmaf(L[k], Rp[k * HID], acc);
        g_Q[e] = acc;
    }
    for (int e = tid; e < NQP * HID * HID; e += stride) {
        int i = e >> 18;
        int rem = e & ((1 << 18) - 1);
        int n = rem >> 9, m = rem & 511;
        const float* L  = RL + i * HID * K_RANK + n * K_RANK;
        const float* Rp = RR + i * K_RANK * HID + m;
        float acc = 0.f;
#pragma unroll 8
        for (int k = 0; k < K_RANK; k++) acc = fmaf(L[k], Rp[k * HID], acc);
        g_R[e] = acc;
    }
    for (int e = tid; e < B_DIM * HID; e += stride) {
        g_h[0][e] = 0.f;
    }
}

extern "C" __global__ void __launch_bounds__(NT, 1)
mogrifier_main(const float* __restrict__ x,
               const float* __restrict__ QL, const float* __restrict__ QR,
               const float* __restrict__ RL, const float* __restrict__ RR,
               const float* __restrict__ Wih, const float* __restrict__ Whh,
               const float* __restrict__ bih, const float* __restrict__ bhh,
               float* __restrict__ out) {
    extern __shared__ float smem[];
    float* As0   = smem;               // xx / mog A tile (persists into gates)
    float* As1   = smem + ABUF;        // h tile (gates)
    float* Wring = smem + 2 * ABUF;

    const int tid  = (int)threadIdx.x;
    const int lane = tid & 31, wpid = tid >> 5;
    const int rt = blockIdx.x & 3, ct = (int)blockIdx.x >> 2;
    const int r0 = rt * 32, j0 = ct * 16;

    // warp = 16 rows x 4 cols; thread = rows {rArel, rArel+8} x 1 col
    const int row8  = lane >> 2;             // 0..7
    const int col_l = lane & 3;              // 0..3
    const int rg = wpid & 1, cg = wpid >> 1; // 2 rowgroups x 4 colgroups
    const int rArel = rg * 16 + row8;
    const int jbase = j0 + cg * 4;
    const int j = jbase + col_l;
    float* myW = Wring + wpid * WWARP_F;
    unsigned int epoch = 0;

    precompute(QL, QR, RL, RR);

    // biases: col-only now (4 regs)
    const float bs0 = bih[j]        + bhh[j];
    const float bs1 = bih[512 + j]  + bhh[512 + j];
    const float bs2 = bih[1024 + j] + bhh[1024 + j];
    const float bs3 = bih[1536 + j] + bhh[1536 + j];

    const float* Q0 = g_Q;
    const float* Q1 = g_Q + HID * HID;
    const float* R0 = g_R;
    const float* R1 = g_R + HID * HID;

    const int rA = r0 + rArel, rB = rA + 8;
    const int idxA = rA * HID + j, idxB = rB * HID + j;

    float cA = 0.f, cB = 0.f;
    float hA = 0.f, hB = 0.f;
    float xxA, xxB;

    full_barrier(epoch);                 // Q/R ready everywhere
    mogw_issue(myW, Q0, jbase, lane);    // prefetch P1 weights

    float* tail = out + (size_t)S_LEN * B_DIM * HID;

    for (int t = 0; t < S_LEN; t++) {
        float* hc = g_h[t & 1];
        float* hn = g_h[(t + 1) & 1];
        const float* xt = x + (size_t)t * B_DIM * HID;

        // P1: xx = 2*sig(h @ Q0^T) * x[t]
        float mA = __ldcs(xt + idxA);
        float mB = __ldcs(xt + idxB);
        mog_phase(As0, myW, hc, r0, rArel, col_l, tid, mA, mB, xxA, xxB);
        __stcg(g_xx + idxA, xxA);
        __stcg(g_xx + idxB, xxB);
        mogw_issue(myW, R0, jbase, lane);        // prefetch P2 W
        row_barrier(epoch, rt);

        // P2: h = 2*sig(xx @ R0^T) * h
        mog_phase(As0, myW, g_xx, r0, rArel, col_l, tid, hA, hB, hA, hB);
        __stcg(hc + idxA, hA);
        __stcg(hc + idxB, hB);
        mogw_issue(myW, Q1, jbase, lane);        // prefetch P3 W
        row_barrier(epoch, rt);

        // P3: xx = 2*sig(h @ Q1^T) * xx
        mog_phase(As0, myW, hc, r0, rArel, col_l, tid, xxA, xxB, xxA, xxB);
        __stcg(g_xx + idxA, xxA);
        __stcg(g_xx + idxB, xxB);
        mogw_issue(myW, R1, jbase, lane);        // prefetch P4 W
        row_barrier(epoch, rt);

        // P4: h = 2*sig(xx @ R1^T) * h   (A = post-P3 xx -> As0 persists)
        mog_phase(As0, myW, g_xx, r0, rArel, col_l, tid, hA, hB, hA, hB);
        __stcg(hc + idxA, hA);
        __stcg(hc + idxB, hB);
        gw_issue(myW,           Wih, jbase, 0,  lane);   // gates chunk 0
        gw_issue(myW + WSLOT_F, Wih, jbase, 64, lane);   // gates chunk 1
        row_barrier(epoch, rt);

        // P5: gates = xx@Wih^T + h@Whh^T + b ; LSTM pointwise.
        // As0 still holds the post-P3 xx tile (P4 staged the same data).
        {
            stageA_full(As1, hc, r0, tid);        // h tile in background

            u64 accA[4], accB[4];
#pragma unroll
            for (int s = 0; s < 4; s++) { accA[s] = 0ull; accB[s] = 0ull; }

            const float4* Ax0 = reinterpret_cast<const float4*>(As0 + rArel * APITCH);
            const float4* Ax1 = reinterpret_cast<const float4*>(As0 + (rArel + 8) * APITCH);
            const float4* Ah0 = reinterpret_cast<const float4*>(As1 + rArel * APITCH);
            const float4* Ah1 = reinterpret_cast<const float4*>(As1 + (rArel + 8) * APITCH);

#pragma unroll 1
            for (int c = 0; c < 16; c++) {           // 16 chunks of 64 k
                if (c < 2)       cp_waitg<2>();
                else if (c < 15) cp_waitg<1>();
                else             cp_waitg<0>();
                __syncwarp();
                if (c == 8) __syncthreads();          // As1 collectively staged
                const float4* a0p = ((c < 8) ? Ax0 : Ah0) + (c & 7) * 16;
                const float4* a1p = ((c < 8) ? Ax1 : Ah1) + (c & 7) * 16;
                const float4* W4 =
                    reinterpret_cast<const float4*>(myW + (c & 1) * WSLOT_F);
#pragma unroll
                for (int kk = 0; kk < 16; kk++) {
                    F4 a0, a1;
                    a0.f = a0p[kk];
                    a1.f = a1p[kk];
                    F4 w;
                    w.f = W4[0 * 68 + col_l * 17 + kk];
                    ffma2(accA[0], a0.d.x, w.d.x); ffma2(accA[0], a0.d.y, w.d.y);
                    ffma2(accB[0], a1.d.x, w.d.x); ffma2(accB[0], a1.d.y, w.d.y);
                    w.f = W4[1 * 68 + col_l * 17 + kk];
                    ffma2(accA[1], a0.d.x, w.d.x); ffma2(accA[1], a0.d.y, w.d.y);
                    ffma2(accB[1], a1.d.x, w.d.x); ffma2(accB[1], a1.d.y, w.d.y);
                    w.f = W4[2 * 68 + col_l * 17 + kk];
                    ffma2(accA[2], a0.d.x, w.d.x); ffma2(accA[2], a0.d.y, w.d.y);
                    ffma2(accB[2], a1.d.x, w.d.x); ffma2(accB[2], a1.d.y, w.d.y);
                    w.f = W4[3 * 68 + col_l * 17 + kk];
                    ffma2(accA[3], a0.d.x, w.d.x); ffma2(accA[3], a0.d.y, w.d.y);
                    ffma2(accB[3], a1.d.x, w.d.x); ffma2(accB[3], a1.d.y, w.d.y);
                }
                if (c + 2 < 16) {
                    int cn = c + 2;
                    gw_issue(myW + (cn & 1) * WSLOT_F,
                             (cn < 8) ? Wih : Whh, jbase,
                             (cn & 7) * 64, lane);
                }
            }

            float igA = pairsum(accA[0]) + bs0;
            float fgA = pairsum(accA[1]) + bs1;
            float ggA = pairsum(accA[2]) + bs2;
            float ogA = pairsum(accA[3]) + bs3;
            float igB = pairsum(accB[0]) + bs0;
            float fgB = pairsum(accB[1]) + bs1;
            float ggB = pairsum(accB[2]) + bs2;
            float ogB = pairsum(accB[3]) + bs3;

            cA = sigf(fgA) * cA + sigf(igA) * tanhf(ggA);
            hA = sigf(ogA) * tanhf(cA);
            cB = sigf(fgB) * cB + sigf(igB) * tanhf(ggB);
            hB = sigf(ogB) * tanhf(cB);

            __stcg(hn + idxA, hA);
            __stcg(hn + idxB, hB);
            float* op = out + (size_t)t * B_DIM * HID;
            op[idxA] = hA;
            op[idxB] = hB;
            if (t == S_LEN - 1) {
                tail[idxA] = hA;  tail[B_DIM * HID + idxA] = cA;
                tail[idxB] = hB;  tail[B_DIM * HID + idxB] = cB;
            }
        }
        mogw_issue(myW, Q0, jbase, lane);        // prefetch next-step P1 W
        row_barrier(epoch, rt);
    }
    cp_waitg<0>();                                // drain dangling prefetch
}

extern "C" void kernel_launch(void* const* d_in, const int* in_sizes, int n_in,
                              void* d_out, int out_size) {
    const float* x   = (const float*)d_in[0];
    const float* QL  = (const float*)d_in[1];
    const float* QR  = (const float*)d_in[2];
    const float* RL  = (const float*)d_in[3];
    const float* RR  = (const float*)d_in[4];
    const float* Wih = (const float*)d_in[5];
    const float* Whh = (const float*)d_in[6];
    const float* bih = (const float*)d_in[7];
    const float* bhh = (const float*)d_in[8];
    (void)in_sizes; (void)n_in; (void)out_size;

    cudaFuncSetAttribute(mogrifier_main,
                         cudaFuncAttributeMaxDynamicSharedMemorySize, SMEM_BYTES);

    mg_init<<<1, 128>>>();
    mogrifier_main<<<GRID_BLOCKS, NT, SMEM_BYTES>>>(x, QL, QR, RL, RR,
                                                    Wih, Whh, bih, bhh,
                                                    (float*)d_out);
}

// round 15
// speedup vs baseline: 1.0695x; 1.0695x over previous
#include <cuda_runtime.h>

// ---------------------------------------------------------------------------
// MogrifierRNN persistent kernel, round 13.  (base = round 11, best so far)
//   - k-SPLIT: NT=512, two 8-warp k-groups, each computing partial dots over
//     its own 256-k half => traffic identical to R11, warps/SMSP 2->4
//   - group-scoped staging + named barriers (bar.sync 1+g, 256)
//   - smem reduction: group1 publishes partials, group0 finalizes (owns c/h/xx)
//   - everything else proven: 32x16 tile, direct-poll row barriers, cp.async
//     prefetch ring, FFMA2, gates As0 reuse
// ---------------------------------------------------------------------------

#define S_LEN 512
#define B_DIM 128
#define HID   512
#define K_RANK 256
#define NQP   2

#define GRID_BLOCKS 128
#define NT          512
#define APITCH      516                 // conflict-free pitch (floats)
#define ABUF        (32 * APITCH)       // 16512 floats
#define WSLOT_F     512                 // 2KB slot
#define WWARP_F     (2 * WSLOT_F)
#define WRING_F     (16 * WWARP_F)      // 16384 floats = 64KB
#define SCRATCH_F   (256 * 9)           // 2304 floats (pad-9, conflict-free)
#define SMEM_FLOATS (2 * ABUF + WRING_F + SCRATCH_F)   // 51712
#define SMEM_BYTES  (SMEM_FLOATS * 4)                  // 206,848 B
#define BAR_STRIDE  32

typedef unsigned long long u64;

// ------------------------- device scratch ----------------------------------
__device__ float g_Q[NQP * HID * HID];   // Q[i][m][n]
__device__ float g_R[NQP * HID * HID];   // R[i][n][m]
__device__ float g_xx[B_DIM * HID];
__device__ float g_h[2][B_DIM * HID];
__device__ unsigned int g_arrive[GRID_BLOCKS * BAR_STRIDE];
__device__ unsigned int g_go_full;

__global__ void mg_init() {
    int i = (int)threadIdx.x;
    if (i < GRID_BLOCKS) g_arrive[i * BAR_STRIDE] = 0u;
    if (i == 0) g_go_full = 0u;
}

__device__ __forceinline__ float sigf(float v) {
    return 1.0f / (1.0f + __expf(-v));
}

// ---- packed fp32x2 FMA ------------------------------------------------------
union F4 { float4 f; ulonglong2 d; };

__device__ __forceinline__ void ffma2(u64& acc, u64 a, u64 b) {
    asm("fma.rn.f32x2 %0, %1, %2, %0;" : "+l"(acc) : "l"(a), "l"(b));
}
__device__ __forceinline__ float pairsum(u64 p) {
    return __uint_as_float((unsigned)p) + __uint_as_float((unsigned)(p >> 32));
}

// ---- cp.async ---------------------------------------------------------------
__device__ __forceinline__ void cpa16(float* dst_smem, const float* src) {
    unsigned d = (unsigned)__cvta_generic_to_shared(dst_smem);
    asm volatile("cp.async.cg.shared.global [%0], [%1], 16;"
                 :: "r"(d), "l"(src) : "memory");
}
__device__ __forceinline__ void cp_commit() {
    asm volatile("cp.async.commit_group;" ::: "memory");
}
template <int N> __device__ __forceinline__ void cp_waitg() {
    asm volatile("cp.async.wait_group %0;" :: "n"(N) : "memory");
}

// ---- barriers ---------------------------------------------------------------
__device__ __forceinline__ unsigned int ld_acq(const unsigned int* p) {
    unsigned int v;
    asm volatile("ld.acquire.gpu.global.u32 %0, [%1];"
                 : "=r"(v) : "l"(p) : "memory");
    return v;
}
__device__ __forceinline__ void st_rel(unsigned int* p, unsigned int v) {
    asm volatile("st.release.gpu.global.u32 [%0], %1;"
                 :: "l"(p), "r"(v) : "memory");
}
__device__ __forceinline__ void bar_group(int g) {
    asm volatile("bar.sync %0, %1;" :: "r"(1 + g), "r"(256) : "memory");
}

// Row-group barrier: the 32 blocks sharing rt (= blockIdx.x & 3). Direct-poll.
__device__ __forceinline__ void row_barrier(unsigned int& epoch, int rt) {
    epoch++;
    __syncthreads();
    if (threadIdx.x == 0) st_rel(&g_arrive[blockIdx.x * BAR_STRIDE], epoch);
    if (threadIdx.x < 32) {
        while (ld_acq(&g_arrive[(rt + 4 * threadIdx.x) * BAR_STRIDE]) < epoch) { }
    }
    __syncthreads();
}

// Full-grid barrier (once, after precompute).
__device__ __forceinline__ void full_barrier(unsigned int& epoch) {
    epoch++;
    __syncthreads();
    if (blockIdx.x == 0) {
        if (threadIdx.x == 0) st_rel(&g_arrive[0], epoch);
        if (threadIdx.x < GRID_BLOCKS) {
            while (ld_acq(&g_arrive[threadIdx.x * BAR_STRIDE]) < epoch) { }
        }
        __syncthreads();
        if (threadIdx.x == 0) st_rel(&g_go_full, epoch);
    } else {
        if (threadIdx.x == 0) {
            st_rel(&g_arrive[blockIdx.x * BAR_STRIDE], epoch);
            while (ld_acq(&g_go_full) < epoch) { }
        }
        __syncthreads();
    }
}

// ---- staging ----------------------------------------------------------------
// Mog W prefetch: this warp's 2 col rows, OWN k-half only. One group.
__device__ __forceinline__ void mogw_issue(float* myW, const float* W,
                                           int jA, int jB, int g, int lane) {
#pragma unroll
    for (int i = 0; i < 4; i++) {
        int f = lane + 32 * i;           // 0..127 f4
        int rr = f >> 6, q = f & 63;
        int rowj = rr ? jB : jA;
        cpa16(myW + f * 4, W + rowj * HID + g * 256 + q * 4);
    }
    cp_commit();
}

// Gates W chunk: 8 rows (4 gates x cols jA,jB) x 64 k. One group.
// Slot: row rr = gate*2+ab at f4 [rr*16, rr*16+16).
__device__ __forceinline__ void gw_issue(float* slot, const float* Wsrc,
                                         int jA, int jB, int kc, int lane) {
#pragma unroll
    for (int i = 0; i < 4; i++) {
        int f = lane + 32 * i;           // 0..127 f4
        int rr = f >> 4, q = f & 15;
        int gate = rr >> 1;
        int col = (rr & 1) ? jB : jA;
        cpa16(slot + f * 4, Wsrc + (gate * HID + col) * HID + kc + q * 4);
    }
    cp_commit();
}

// Mogrifier partial: stage own A half, wait, compute 64 k4 partial dot-pair.
// Entering: this warp's W (1 group) already issued pre-barrier.
__device__ __forceinline__ void mog_partial(float* As, const float* myW,
                                            const float* Aglob, int r0, int g,
                                            int gtid, int lane,
                                            float& p0, float& p1) {
#pragma unroll
    for (int i = 0; i < 8; i++) {
        int e = gtid + 256 * i;          // 0..2047 f4 of own half
        int row = e >> 6, q = e & 63;
        cpa16(As + row * APITCH + g * 256 + q * 4,
              Aglob + (r0 + row) * HID + g * 256 + q * 4);
    }
    cp_commit();
    cp_waitg<0>();                       // own W + own A part
    bar_group(g);                        // group's A half fully staged

    u64 c0x = 0ull, c0y = 0ull, c1x = 0ull, c1y = 0ull;
    const float4* A4 = reinterpret_cast<const float4*>(As + lane * APITCH) + g * 64;
    const float4* W4 = reinterpret_cast<const float4*>(myW);
#pragma unroll 8
    for (int kk = 0; kk < 64; kk++) {
        F4 a, w0, w1;
        a.f  = A4[kk];
        w0.f = W4[kk];
        w1.f = W4[64 + kk];
        ffma2(c0x, a.d.x, w0.d.x); ffma2(c0y, a.d.y, w0.d.y);
        ffma2(c1x, a.d.x, w1.d.x); ffma2(c1y, a.d.y, w1.d.y);
    }
    p0 = pairsum(c0x) + pairsum(c0y);
    p1 = pairsum(c1x) + pairsum(c1y);
}

// One-time precompute of Q = QL@QR, R = RL@RR; zero h0.
__device__ void precompute(const float* QL, const float* QR,
                           const float* RL, const float* RR) {
    const int tid = (int)blockIdx.x * NT + (int)threadIdx.x;
    const int stride = GRID_BLOCKS * NT;
    for (int e = tid; e < NQP * HID * HID; e += stride) {
        int i = e >> 18;
        int rem = e & ((1 << 18) - 1);
        int m = rem >> 9, n = rem & 511;
        const float* L  = QL + i * HID * K_RANK + m * K_RANK;
        const float* Rp = QR + i * K_RANK * HID + n;
        float acc = 0.f;
#pragma unroll 8
        for (int k = 0; k < K_RANK; k++) acc = fmaf(L[k], Rp[k * HID], acc);
        g_Q[e] = acc;
    }
    for (int e = tid; e < NQP * HID * HID; e += stride) {
        int i = e >> 18;
        int rem = e & ((1 << 18) - 1);
        int n = rem >> 9, m = rem & 511;
        const float* L  = RL + i * HID * K_RANK + n * K_RANK;
        const float* Rp = RR + i * K_RANK * HID + m;
        float acc = 0.f;
#pragma unroll 8
        for (int k = 0; k < K_RANK; k++) acc = fmaf(L[k], Rp[k * HID], acc);
        g_R[e] = acc;
    }
    for (int e = tid; e < B_DIM * HID; e += stride) {
        g_h[0][e] = 0.f;
    }
}

extern "C" __global__ void __launch_bounds__(NT, 1)
mogrifier_main(const float* __restrict__ x,
               const float* __restrict__ QL, const float* __restrict__ QR,
               const float* __restrict__ RL, const float* __restrict__ RR,
               const float* __restrict__ Wih, const float* __restrict__ Whh,
               const float* __restrict__ bih, const float* __restrict__ bhh,
               float* __restrict__ out) {
    extern __shared__ float smem[];
    float* As0     = smem;               // xx / mog tile (persists into gates)
    float* As1     = smem + ABUF;        // h tile (gates)
    float* Wring   = smem + 2 * ABUF;
    float* scratch = smem + 2 * ABUF + WRING_F;

    const int tid  = (int)threadIdx.x;
    const int lane = tid & 31, wpid = tid >> 5;     // 16 warps
    const int g    = wpid >> 3;                     // k-group 0/1
    const int wloc = wpid & 7;                      // colpair within group
    const int gtid = tid & 255;                     // thread id within group
    const int rt = blockIdx.x & 3, ct = (int)blockIdx.x >> 2;
    const int r0 = rt * 32, j0 = ct * 16;
    const int jA = j0 + 2 * wloc, jB = jA + 1;
    float* myW = Wring + wpid * WWARP_F;
    unsigned int epoch = 0;

    precompute(QL, QR, RL, RR);

    const float bs0 = bih[jA]        + bhh[jA];
    const float bs1 = bih[512 + jA]  + bhh[512 + jA];
    const float bs2 = bih[1024 + jA] + bhh[1024 + jA];
    const float bs3 = bih[1536 + jA] + bhh[1536 + jA];
    const float bt0 = bih[jB]        + bhh[jB];
    const float bt1 = bih[512 + jB]  + bhh[512 + jB];
    const float bt2 = bih[1024 + jB] + bhh[1024 + jB];
    const float bt3 = bih[1536 + jB] + bhh[1536 + jB];

    const float* Q0 = g_Q;
    const float* Q1 = g_Q + HID * HID;
    const float* R0 = g_R;
    const float* R1 = g_R + HID * HID;

    const int b = r0 + lane;
    const int idxA = b * HID + jA, idxB = b * HID + jB;

    // group0 owns all recurrent state
    float cA = 0.f, cB = 0.f, hA = 0.f, hB = 0.f, xxA = 0.f, xxB = 0.f;
    float p0, p1;

    full_barrier(epoch);                      // Q/R ready everywhere
    mogw_issue(myW, Q0, jA, jB, g, lane);     // prefetch P1 W (own k-half)

    float* tail = out + (size_t)S_LEN * B_DIM * HID;

    for (int t = 0; t < S_LEN; t++) {
        float* hc = g_h[t & 1];
        float* hn = g_h[(t + 1) & 1];
        const float* xt = x + (size_t)t * B_DIM * HID;

        // ---- P1: xx = 2*sig(h @ Q0^T) * x[t] ----
        float mA = 0.f, mB = 0.f;
        if (!g) { mA = __ldcs(xt + idxA); mB = __ldcs(xt + idxB); }
        mog_partial(As0, myW, hc, r0, g, gtid, lane, p0, p1);
        if (g) { scratch[gtid * 9 + 0] = p0; scratch[gtid * 9 + 1] = p1; }
        __syncthreads();
        if (!g) {
            xxA = 2.0f * sigf(p0 + scratch[gtid * 9 + 0]) * mA;
            xxB = 2.0f * sigf(p1 + scratch[gtid * 9 + 1]) * mB;
            __stcg(g_xx + idxA, xxA);
            __stcg(g_xx + idxB, xxB);
        }
        mogw_issue(myW, R0, jA, jB, g, lane);
        row_barrier(epoch, rt);

        // ---- P2: h = 2*sig(xx @ R0^T) * h ----
        mog_partial(As0, myW, g_xx, r0, g, gtid, lane, p0, p1);
        if (g) { scratch[gtid * 9 + 0] = p0; scratch[gtid * 9 + 1] = p1; }
        __syncthreads();
        if (!g) {
            hA = 2.0f * sigf(p0 + scratch[gtid * 9 + 0]) * hA;
            hB = 2.0f * sigf(p1 + scratch[gtid * 9 + 1]) * hB;
            __stcg(hc + idxA, hA);
            __stcg(hc + idxB, hB);
        }
        mogw_issue(myW, Q1, jA, jB, g, lane);
        row_barrier(epoch, rt);

        // ---- P3: xx = 2*sig(h @ Q1^T) * xx ----
        mog_partial(As0, myW, hc, r0, g, gtid, lane, p0, p1);
        if (g) { scratch[gtid * 9 + 0] = p0; scratch[gtid * 9 + 1] = p1; }
        __syncthreads();
        if (!g) {
            xxA = 2.0f * sigf(p0 + scratch[gtid * 9 + 0]) * xxA;
            xxB = 2.0f * sigf(p1 + scratch[gtid * 9 + 1]) * xxB;
            __stcg(g_xx + idxA, xxA);
            __stcg(g_xx + idxB, xxB);
        }
        mogw_issue(myW, R1, jA, jB, g, lane);
        row_barrier(epoch, rt);

        // ---- P4: h = 2*sig(xx @ R1^T) * h  (stages As0 with post-P3 xx) ----
        mog_partial(As0, myW, g_xx, r0, g, gtid, lane, p0, p1);
        if (g) { scratch[gtid * 9 + 0] = p0; scratch[gtid * 9 + 1] = p1; }
        __syncthreads();
        if (!g) {
            hA = 2.0f * sigf(p0 + scratch[gtid * 9 + 0]) * hA;
            hB = 2.0f * sigf(p1 + scratch[gtid * 9 + 1]) * hB;
            __stcg(hc + idxA, hA);
            __stcg(hc + idxB, hB);
        }
        gw_issue(myW,           Wih, jA, jB, g * 256,      lane);  // chunk 0
        gw_issue(myW + WSLOT_F, Wih, jA, jB, g * 256 + 64, lane);  // chunk 1
        row_barrier(epoch, rt);

        // ---- P5: gates (own k-half of Wih then Whh); As0 reused ----
        {
            // stage own k-half of the h tile into As1
#pragma unroll
            for (int i = 0; i < 8; i++) {
                int e = gtid + 256 * i;
                int row = e >> 6, q = e & 63;
                cpa16(As1 + row * APITCH + g * 256 + q * 4,
                      hc + (r0 + row) * HID + g * 256 + q * 4);
            }
            cp_commit();

            u64 acc[8];
#pragma unroll
            for (int s = 0; s < 8; s++) acc[s] = 0ull;

            const float4* Ax =
                reinterpret_cast<const float4*>(As0 + lane * APITCH) + g * 64;
            const float4* Ah =
                reinterpret_cast<const float4*>(As1 + lane * APITCH) + g * 64;

#pragma unroll 1
            for (int c = 0; c < 8; c++) {
                if (c < 2)       cp_waitg<2>();
                else if (c < 7)  cp_waitg<1>();
                else             cp_waitg<0>();
                __syncwarp();
                if (c == 4) bar_group(g);     // own As1 half fully staged
                const float4* A4 = ((c < 4) ? Ax : Ah) + (c & 3) * 16;
                const float4* W4 =
                    reinterpret_cast<const float4*>(myW + (c & 1) * WSLOT_F);
#pragma unroll
                for (int kk = 0; kk < 16; kk++) {
                    F4 a; a.f = A4[kk];
                    F4 v;
                    v.f = W4[0 * 16 + kk];
                    ffma2(acc[0], a.d.x, v.d.x); ffma2(acc[0], a.d.y, v.d.y);
                    v.f = W4[1 * 16 + kk];
                    ffma2(acc[4], a.d.x, v.d.x); ffma2(acc[4], a.d.y, v.d.y);
                    v.f = W4[2 * 16 + kk];
                    ffma2(acc[1], a.d.x, v.d.x); ffma2(acc[1], a.d.y, v.d.y);
                    v.f = W4[3 * 16 + kk];
                    ffma2(acc[5], a.d.x, v.d.x); ffma2(acc[5], a.d.y, v.d.y);
                    v.f = W4[4 * 16 + kk];
                    ffma2(acc[2], a.d.x, v.d.x); ffma2(acc[2], a.d.y, v.d.y);
                    v.f = W4[5 * 16 + kk];
                    ffma2(acc[6], a.d.x, v.d.x); ffma2(acc[6], a.d.y, v.d.y);
                    v.f = W4[6 * 16 + kk];
                    ffma2(acc[3], a.d.x, v.d.x); ffma2(acc[3], a.d.y, v.d.y);
                    v.f = W4[7 * 16 + kk];
                    ffma2(acc[7], a.d.x, v.d.x); ffma2(acc[7], a.d.y, v.d.y);
                }
                if (c + 2 < 8) {
                    int cn = c + 2;
                    const float* Wsrc = (cn < 4) ? Wih : Whh;
                    gw_issue(myW + (cn & 1) * WSLOT_F, Wsrc, jA, jB,
                             g * 256 + (cn & 3) * 64, lane);
                }
            }

            float pr[8];
#pragma unroll
            for (int s = 0; s < 8; s++) pr[s] = pairsum(acc[s]);

            if (g) {
#pragma unroll
                for (int s = 0; s < 8; s++) scratch[gtid * 9 + s] = pr[s];
            }
            __syncthreads();
            if (!g) {
                float igA = pr[0] + scratch[gtid * 9 + 0] + bs0;
                float fgA = pr[1] + scratch[gtid * 9 + 1] + bs1;
                float ggA = pr[2] + scratch[gtid * 9 + 2] + bs2;
                float ogA = pr[3] + scratch[gtid * 9 + 3] + bs3;
                float igB = pr[4] + scratch[gtid * 9 + 4] + bt0;
                float fgB = pr[5] + scratch[gtid * 9 + 5] + bt1;
                float ggB = pr[6] + scratch[gtid * 9 + 6] + bt2;
                float ogB = pr[7] + scratch[gtid * 9 + 7] + bt3;

                cA = sigf(fgA) * cA + sigf(igA) * tanhf(ggA);
                hA = sigf(ogA) * tanhf(cA);
                cB = sigf(fgB) * cB + sigf(igB) * tanhf(ggB);
                hB = sigf(ogB) * tanhf(cB);

                __stcg(hn + idxA, hA);
                __stcg(hn + idxB, hB);
                float* op = out + (size_t)t * B_DIM * HID;
                op[idxA] = hA;
                op[idxB] = hB;
                if (t == S_LEN - 1) {
                    tail[idxA] = hA;  tail[B_DIM * HID + idxA] = cA;
                    tail[idxB] = hB;  tail[B_DIM * HID + idxB] = cB;
                }
            }
        }
        mogw_issue(myW, Q0, jA, jB, g, lane);   // prefetch next-step P1 W
        row_barrier(epoch, rt);
    }
    cp_waitg<0>();                               // drain dangling prefetch
}

extern "C" void kernel_launch(void* const* d_in, const int* in_sizes, int n_in,
                              void* d_out, int out_size) {
    const float* x   = (const float*)d_in[0];
    const float* QL  = (const float*)d_in[1];
    const float* QR  = (const float*)d_in[2];
    const float* RL  = (const float*)d_in[3];
    const float* RR  = (const float*)d_in[4];
    const float* Wih = (const float*)d_in[5];
    const float* Whh = (const float*)d_in[6];
    const float* bih = (const float*)d_in[7];
    const float* bhh = (const float*)d_in[8];
    (void)in_sizes; (void)n_in; (void)out_size;

    cudaFuncSetAttribute(mogrifier_main,
                         cudaFuncAttributeMaxDynamicSharedMemorySize, SMEM_BYTES);

    mg_init<<<1, 128>>>();
    mogrifier_main<<<GRID_BLOCKS, NT, SMEM_BYTES>>>(x, QL, QR, RL, RR,
                                                    Wih, Whh, bih, bhh,
                                                    (float*)d_out);
}

// round 16
// speedup vs baseline: 1.1357x; 1.0619x over previous
#include <cuda_runtime.h>

// ---------------------------------------------------------------------------
// MogrifierRNN persistent kernel, round 15.  (base = round 13)
//   - mog G2 remap: warp = 8 cols x 4 rowslots, thread = 1 col x 8 rows
//     => W LDS 128B-dense (1 cyc/kk, was 8x16B broadcasts), A LDS 64B N=1
//     => mog crossbar 24.6K -> 9.2K cyc/step
//   - 8 k-groups (64k) for mog, group A-slice staging, 8-way scratch reduce
//   - mog multiplicands (x/h/xx) via prefetched __ldcs; c stays in registers
//     in the UNCHANGED R13 gates layout
//   - gates / barriers / prefetch ring identical to R13
// ---------------------------------------------------------------------------

#define S_LEN 512
#define B_DIM 128
#define HID   512
#define K_RANK 256
#define NQP   2

#define GRID_BLOCKS 128
#define NT          512
#define APITCH      516                 // floats; 129 f4 per row
#define ABUF        (32 * APITCH)       // 16512 floats
#define WSLOT_F     512                 // 2KB slot
#define WWARP_F     (2 * WSLOT_F)
#define WRING_F     (16 * WWARP_F)      // 16384 floats
#define SCRATCH_F   (512 * 9)           // 4608 floats
#define SMEM_FLOATS (2 * ABUF + WRING_F + SCRATCH_F)   // 54016
#define SMEM_BYTES  (SMEM_FLOATS * 4)                  // 216,064 B
#define BAR_STRIDE  32

typedef unsigned long long u64;

// ------------------------- device scratch ----------------------------------
__device__ float g_Q[NQP * HID * HID];   // Q[i][m][n]
__device__ float g_R[NQP * HID * HID];   // R[i][n][m]
__device__ float g_xx[B_DIM * HID];
__device__ float g_h[2][B_DIM * HID];
__device__ unsigned int g_arrive[GRID_BLOCKS * BAR_STRIDE];
__device__ unsigned int g_go_full;

__global__ void mg_init() {
    int i = (int)threadIdx.x;
    if (i < GRID_BLOCKS) g_arrive[i * BAR_STRIDE] = 0u;
    if (i == 0) g_go_full = 0u;
}

__device__ __forceinline__ float sigf(float v) {
    return 1.0f / (1.0f + __expf(-v));
}

// ---- packed fp32x2 FMA ------------------------------------------------------
union F4 { float4 f; ulonglong2 d; };

__device__ __forceinline__ void ffma2(u64& acc, u64 a, u64 b) {
    asm("fma.rn.f32x2 %0, %1, %2, %0;" : "+l"(acc) : "l"(a), "l"(b));
}
__device__ __forceinline__ float pairsum(u64 p) {
    return __uint_as_float((unsigned)p) + __uint_as_float((unsigned)(p >> 32));
}

// ---- cp.async ---------------------------------------------------------------
__device__ __forceinline__ void cpa16(float* dst_smem, const float* src) {
    unsigned d = (unsigned)__cvta_generic_to_shared(dst_smem);
    asm volatile("cp.async.cg.shared.global [%0], [%1], 16;"
                 :: "r"(d), "l"(src) : "memory");
}
__device__ __forceinline__ void cp_commit() {
    asm volatile("cp.async.commit_group;" ::: "memory");
}
template <int N> __device__ __forceinline__ void cp_waitg() {
    asm volatile("cp.async.wait_group %0;" :: "n"(N) : "memory");
}

// ---- barriers ---------------------------------------------------------------
__device__ __forceinline__ unsigned int ld_acq(const unsigned int* p) {
    unsigned int v;
    asm volatile("ld.acquire.gpu.global.u32 %0, [%1];"
                 : "=r"(v) : "l"(p) : "memory");
    return v;
}
__device__ __forceinline__ void st_rel(unsigned int* p, unsigned int v) {
    asm volatile("st.release.gpu.global.u32 [%0], %1;"
                 :: "l"(p), "r"(v) : "memory");
}
__device__ __forceinline__ void bar_named(int id, int cnt) {
    asm volatile("bar.sync %0, %1;" :: "r"(id), "r"(cnt) : "memory");
}

// Row-group barrier: the 32 blocks sharing rt (= blockIdx.x & 3). Direct-poll.
__device__ __forceinline__ void row_barrier(unsigned int& epoch, int rt) {
    epoch++;
    __syncthreads();
    if (threadIdx.x == 0) st_rel(&g_arrive[blockIdx.x * BAR_STRIDE], epoch);
    if (threadIdx.x < 32) {
        while (ld_acq(&g_arrive[(rt + 4 * threadIdx.x) * BAR_STRIDE]) < epoch) { }
    }
    __syncthreads();
}

// Full-grid barrier (once, after precompute).
__device__ __forceinline__ void full_barrier(unsigned int& epoch) {
    epoch++;
    __syncthreads();
    if (blockIdx.x == 0) {
        if (threadIdx.x == 0) st_rel(&g_arrive[0], epoch);
        if (threadIdx.x < GRID_BLOCKS) {
            while (ld_acq(&g_arrive[threadIdx.x * BAR_STRIDE]) < epoch) { }
        }
        __syncthreads();
        if (threadIdx.x == 0) st_rel(&g_go_full, epoch);
    } else {
        if (threadIdx.x == 0) {
            st_rel(&g_arrive[blockIdx.x * BAR_STRIDE], epoch);
            while (ld_acq(&g_go_full) < epoch) { }
        }
        __syncthreads();
    }
}

// ---- staging ----------------------------------------------------------------
// Mog W prefetch: this warp's 8 cols x 16 f4 (own 64-k slice), transposed
// into slot layout [col*17 + kk] f4 (pitch-17 => dense conflict-free reads).
__device__ __forceinline__ void mogw_issue(float* myW, const float* W,
                                           int jbase8, int q, int lane) {
#pragma unroll
    for (int i = 0; i < 4; i++) {
        int f = lane + 32 * i;           // 0..127
        int col = f >> 4, kk = f & 15;
        cpa16(myW + (col * 17 + kk) * 4,
              W + (jbase8 + col) * HID + q * 64 + kk * 4);
    }
    cp_commit();
}

// Gates W chunk (R13): 8 rows (4 gates x cols jA,jB) x 64 k. One group.
__device__ __forceinline__ void gw_issue(float* slot, const float* Wsrc,
                                         int jA, int jB, int kc, int lane) {
#pragma unroll
    for (int i = 0; i < 4; i++) {
        int f = lane + 32 * i;           // 0..127 f4
        int rr = f >> 4, qd = f & 15;
        int gate = rr >> 1;
        int col = (rr & 1) ? jB : jA;
        cpa16(slot + f * 4, Wsrc + (gate * HID + col) * HID + kc + qd * 4);
    }
    cp_commit();
}

// Mog G2 phase: Dst[b,j] = 2*sig( A[b,:] . W[j,:] ) * Mul[b,j]
// 16 warps = 2 colgroups(cg) x 8 kgroups(q). thread = 1 col x 8 rows.
__device__ __forceinline__ void mog_g2(float* As, const float* myW, float* scr,
                                       const float* Aglob, const float* Mul,
                                       float* Dst, int r0, int j0,
                                       int q, int qtid, int rs, int gc,
                                       int colL) {
    // stage this group's A slice: 32 rows x k[64q, 64q+64)
#pragma unroll
    for (int i = 0; i < 8; i++) {
        int e = qtid + 64 * i;           // 0..511 f4
        int row = e >> 4, kk = e & 15;
        cpa16(As + row * APITCH + q * 64 + kk * 4,
              Aglob + (r0 + row) * HID + q * 64 + kk * 4);
    }
    cp_commit();

    // finalizing group prefetches multiplicands (hides L2 latency)
    float mul[8];
    if (q == 0) {
#pragma unroll
        for (int i = 0; i < 8; i++)
            mul[i] = __ldcs(Mul + (r0 + 4 * i + rs) * HID + j0 + colL);
    }

    cp_waitg<0>();                       // own W + own A slice
    bar_named(1 + q, 64);                // group's slice fully staged

    u64 acc[8];
#pragma unroll
    for (int i = 0; i < 8; i++) acc[i] = 0ull;

    const float4* A4 = reinterpret_cast<const float4*>(As) + rs * 129 + q * 16;
    const float4* W4 = reinterpret_cast<const float4*>(myW) + gc * 17;
#pragma unroll 4
    for (int kk = 0; kk < 16; kk++) {
        F4 w; w.f = W4[kk];
        F4 a0, a1, a2, a3, a4, a5, a6, a7;
        a0.f = A4[0 * 516 + kk];
        a1.f = A4[1 * 516 + kk];
        a2.f = A4[2 * 516 + kk];
        a3.f = A4[3 * 516 + kk];
        a4.f = A4[4 * 516 + kk];
        a5.f = A4[5 * 516 + kk];
        a6.f = A4[6 * 516 + kk];
        a7.f = A4[7 * 516 + kk];
        ffma2(acc[0], a0.d.x, w.d.x); ffma2(acc[1], a1.d.x, w.d.x);
        ffma2(acc[2], a2.d.x, w.d.x); ffma2(acc[3], a3.d.x, w.d.x);
        ffma2(acc[4], a4.d.x, w.d.x); ffma2(acc[5], a5.d.x, w.d.x);
        ffma2(acc[6], a6.d.x, w.d.x); ffma2(acc[7], a7.d.x, w.d.x);
        ffma2(acc[0], a0.d.y, w.d.y); ffma2(acc[1], a1.d.y, w.d.y);
        ffma2(acc[2], a2.d.y, w.d.y); ffma2(acc[3], a3.d.y, w.d.y);
        ffma2(acc[4], a4.d.y, w.d.y); ffma2(acc[5], a5.d.y, w.d.y);
        ffma2(acc[6], a6.d.y, w.d.y); ffma2(acc[7], a7.d.y, w.d.y);
    }

    float p[8];
#pragma unroll
    for (int i = 0; i < 8; i++) p[i] = pairsum(acc[i]);

    if (q != 0) {
#pragma unroll
        for (int i = 0; i < 8; i++) {
            int o = (4 * i + rs) * 16 + colL;
            scr[o * 9 + q] = p[i];
        }
    }
    __syncthreads();
    if (q == 0) {
#pragma unroll
        for (int i = 0; i < 8; i++) {
            int o = (4 * i + rs) * 16 + colL;
            float s = p[i];
#pragma unroll
            for (int qq = 1; qq < 8; qq++) s += scr[o * 9 + qq];
            float v = 2.0f * sigf(s) * mul[i];
            __stcg(Dst + (r0 + 4 * i + rs) * HID + j0 + colL, v);
        }
    }
}

// One-time precompute of Q = QL@QR, R = RL@RR; zero h0.
__device__ void precompute(const float* QL, const float* QR,
                           const float* RL, const float* RR) {
    const int tid = (int)blockIdx.x * NT + (int)threadIdx.x;
    const int stride = GRID_BLOCKS * NT;
    for (int e = tid; e < NQP * HID * HID; e += stride) {
        int i = e >> 18;
        int rem = e & ((1 << 18) - 1);
        int m = rem >> 9, n = rem & 511;
        const float* L  = QL + i * HID * K_RANK + m * K_RANK;
        const float* Rp = QR + i * K_RANK * HID + n;
        float acc = 0.f;
#pragma unroll 8
        for (int k = 0; k < K_RANK; k++) acc = fmaf(L[k], Rp[k * HID], acc);
        g_Q[e] = acc;
    }
    for (int e = tid; e < NQP * HID * HID; e += stride) {
        int i = e >> 18;
        int rem = e & ((1 << 18) - 1);
        int n = rem >> 9, m = rem & 511;
        const float* L  = RL + i * HID * K_RANK + n * K_RANK;
        const float* Rp = RR + i * K_RANK * HID + m;
        float acc = 0.f;
#pragma unroll 8
        for (int k = 0; k < K_RANK; k++) acc = fmaf(L[k], Rp[k * HID], acc);
        g_R[e] = acc;
    }
    for (int e = tid; e < B_DIM * HID; e += stride) {
        g_h[0][e] = 0.f;
    }
}

extern "C" __global__ void __launch_bounds__(NT, 1)
mogrifier_main(const float* __restrict__ x,
               const float* __restrict__ QL, const float* __restrict__ QR,
               const float* __restrict__ RL, const float* __restrict__ RR,
               const float* __restrict__ Wih, const float* __restrict__ Whh,
               const float* __restrict__ bih, const float* __restrict__ bhh,
               float* __restrict__ out) {
    extern __shared__ float smem[];
    float* As0     = smem;               // xx / mog tile (persists into gates)
    float* As1     = smem + ABUF;        // h tile (gates)
    float* Wring   = smem + 2 * ABUF;
    float* scr     = smem + 2 * ABUF + WRING_F;

    const int tid  = (int)threadIdx.x;
    const int lane = tid & 31, wpid = tid >> 5;     // 16 warps
    const int rt = blockIdx.x & 3, ct = (int)blockIdx.x >> 2;
    const int r0 = rt * 32, j0 = ct * 16;
    float* myW = Wring + wpid * WWARP_F;
    unsigned int epoch = 0;

    // ---- mog G2 indices: 2 colgroups x 8 kgroups ----
    const int q  = wpid >> 1;                        // kgroup 0..7
    const int cg = wpid & 1;                         // colgroup 0/1
    const int qtid = (cg << 5) | lane;               // 0..63 within kgroup
    const int rs = lane >> 3;                        // rowslot 0..3
    const int gc = lane & 7;                         // col within 8
    const int jbase8 = j0 + 8 * cg;
    const int colL = 8 * cg + gc;                    // 0..15

    // ---- gates indices (R13): 2 kgroups of 8 warps ----
    const int gg = wpid >> 3;                        // gates kgroup 0/1
    const int wloc = wpid & 7;
    const int gtid = tid & 255;
    const int jA = j0 + 2 * wloc, jB = jA + 1;

    precompute(QL, QR, RL, RR);

    const float bs0 = bih[jA]        + bhh[jA];
    const float bs1 = bih[512 + jA]  + bhh[512 + jA];
    const float bs2 = bih[1024 + jA] + bhh[1024 + jA];
    const float bs3 = bih[1536 + jA] + bhh[1536 + jA];
    const float bt0 = bih[jB]        + bhh[jB];
    const float bt1 = bih[512 + jB]  + bhh[512 + jB];
    const float bt2 = bih[1024 + jB] + bhh[1024 + jB];
    const float bt3 = bih[1536 + jB] + bhh[1536 + jB];

    const float* Q0 = g_Q;
    const float* Q1 = g_Q + HID * HID;
    const float* R0 = g_R;
    const float* R1 = g_R + HID * HID;

    const int b = r0 + lane;
    const int idxA = b * HID + jA, idxB = b * HID + jB;

    float cA = 0.f, cB = 0.f;            // cell state, registers (gates layout)

    full_barrier(epoch);                      // Q/R ready everywhere
    mogw_issue(myW, Q0, jbase8, q, lane);     // prefetch P1 W

    float* tail = out + (size_t)S_LEN * B_DIM * HID;

    for (int t = 0; t < S_LEN; t++) {
        float* hc = g_h[t & 1];
        float* hn = g_h[(t + 1) & 1];
        const float* xt = x + (size_t)t * B_DIM * HID;

        // P1: xx = 2*sig(h @ Q0^T) * x[t]
        mog_g2(As0, myW, scr, hc, xt, g_xx, r0, j0, q, qtid, rs, gc, colL);
        mogw_issue(myW, R0, jbase8, q, lane);
        row_barrier(epoch, rt);

        // P2: h = 2*sig(xx @ R0^T) * h
        mog_g2(As0, myW, scr, g_xx, hc, hc, r0, j0, q, qtid, rs, gc, colL);
        mogw_issue(myW, Q1, jbase8, q, lane);
        row_barrier(epoch, rt);

        // P3: xx = 2*sig(h @ Q1^T) * xx
        mog_g2(As0, myW, scr, hc, g_xx, g_xx, r0, j0, q, qtid, rs, gc, colL);
        mogw_issue(myW, R1, jbase8, q, lane);
        row_barrier(epoch, rt);

        // P4: h = 2*sig(xx @ R1^T) * h   (stages As0 with post-P3 xx)
        mog_g2(As0, myW, scr, g_xx, hc, hc, r0, j0, q, qtid, rs, gc, colL);
        gw_issue(myW,           Wih, jA, jB, gg * 256,      lane);
        gw_issue(myW + WSLOT_F, Wih, jA, jB, gg * 256 + 64, lane);
        row_barrier(epoch, rt);

        // P5: gates (own k-half of Wih then Whh); As0 reused (R13 verbatim)
        {
#pragma unroll
            for (int i = 0; i < 8; i++) {
                int e = gtid + 256 * i;
                int row = e >> 6, qd = e & 63;
                cpa16(As1 + row * APITCH + gg * 256 + qd * 4,
                      hc + (r0 + row) * HID + gg * 256 + qd * 4);
            }
            cp_commit();

            u64 acc[8];
#pragma unroll
            for (int s = 0; s < 8; s++) acc[s] = 0ull;

            const float4* Ax =
                reinterpret_cast<const float4*>(As0 + lane * APITCH) + gg * 64;
            const float4* Ah =
                reinterpret_cast<const float4*>(As1 + lane * APITCH) + gg * 64;

#pragma unroll 1
            for (int c = 0; c < 8; c++) {
                if (c < 2)       cp_waitg<2>();
                else if (c < 7)  cp_waitg<1>();
                else             cp_waitg<0>();
                __syncwarp();
                if (c == 4) bar_named(9 + gg, 256);   // own As1 half staged
                const float4* A4 = ((c < 4) ? Ax : Ah) + (c & 3) * 16;
                const float4* W4 =
                    reinterpret_cast<const float4*>(myW + (c & 1) * WSLOT_F);
#pragma unroll
                for (int kk = 0; kk < 16; kk++) {
                    F4 a; a.f = A4[kk];
                    F4 v;
                    v.f = W4[0 * 16 + kk];
                    ffma2(acc[0], a.d.x, v.d.x); ffma2(acc[0], a.d.y, v.d.y);
                    v.f = W4[1 * 16 + kk];
                    ffma2(acc[4], a.d.x, v.d.x); ffma2(acc[4], a.d.y, v.d.y);
                    v.f = W4[2 * 16 + kk];
                    ffma2(acc[1], a.d.x, v.d.x); ffma2(acc[1], a.d.y, v.d.y);
                    v.f = W4[3 * 16 + kk];
                    ffma2(acc[5], a.d.x, v.d.x); ffma2(acc[5], a.d.y, v.d.y);
                    v.f = W4[4 * 16 + kk];
                    ffma2(acc[2], a.d.x, v.d.x); ffma2(acc[2], a.d.y, v.d.y);
                    v.f = W4[5 * 16 + kk];
                    ffma2(acc[6], a.d.x, v.d.x); ffma2(acc[6], a.d.y, v.d.y);
                    v.f = W4[6 * 16 + kk];
                    ffma2(acc[3], a.d.x, v.d.x); ffma2(acc[3], a.d.y, v.d.y);
                    v.f = W4[7 * 16 + kk];
                    ffma2(acc[7], a.d.x, v.d.x); ffma2(acc[7], a.d.y, v.d.y);
                }
                if (c + 2 < 8) {
                    int cn = c + 2;
                    const float* Wsrc = (cn < 4) ? Wih : Whh;
                    gw_issue(myW + (cn & 1) * WSLOT_F, Wsrc, jA, jB,
                             gg * 256 + (cn & 3) * 64, lane);
                }
            }

            float pr[8];
#pragma unroll
            for (int s = 0; s < 8; s++) pr[s] = pairsum(acc[s]);

            if (gg) {
#pragma unroll
                for (int s = 0; s < 8; s++) scr[gtid * 9 + s] = pr[s];
            }
            __syncthreads();
            if (!gg) {
                float igA = pr[0] + scr[gtid * 9 + 0] + bs0;
                float fgA = pr[1] + scr[gtid * 9 + 1] + bs1;
                float ggA = pr[2] + scr[gtid * 9 + 2] + bs2;
                float ogA = pr[3] + scr[gtid * 9 + 3] + bs3;
                float igB = pr[4] + scr[gtid * 9 + 4] + bt0;
                float fgB = pr[5] + scr[gtid * 9 + 5] + bt1;
                float ggB = pr[6] + scr[gtid * 9 + 6] + bt2;
                float ogB = pr[7] + scr[gtid * 9 + 7] + bt3;

                cA = sigf(fgA) * cA + sigf(igA) * tanhf(ggA);
                float hAv = sigf(ogA) * tanhf(cA);
                cB = sigf(fgB) * cB + sigf(igB) * tanhf(ggB);
                float hBv = sigf(ogB) * tanhf(cB);

                __stcg(hn + idxA, hAv);
                __stcg(hn + idxB, hBv);
                float* op = out + (size_t)t * B_DIM * HID;
                op[idxA] = hAv;
                op[idxB] = hBv;
                if (t == S_LEN - 1) {
                    tail[idxA] = hAv;  tail[B_DIM * HID + idxA] = cA;
                    tail[idxB] = hBv;  tail[B_DIM * HID + idxB] = cB;
                }
            }
        }
        mogw_issue(myW, Q0, jbase8, q, lane);   // prefetch next-step P1 W
        row_barrier(epoch, rt);
    }
    cp_waitg<0>();                               // drain dangling prefetch
}

extern "C" void kernel_launch(void* const* d_in, const int* in_sizes, int n_in,
                              void* d_out, int out_size) {
    const float* x   = (const float*)d_in[0];
    const float* QL  = (const float*)d_in[1];
    const float* QR  = (const float*)d_in[2];
    const float* RL  = (const float*)d_in[3];
    const float* RR  = (const float*)d_in[4];
    const float* Wih = (const float*)d_in[5];
    const float* Whh = (const float*)d_in[6];
    const float* bih = (const float*)d_in[7];
    const float* bhh = (const float*)d_in[8];
    (void)in_sizes; (void)n_in; (void)out_size;

    cudaFuncSetAttribute(mogrifier_main,
                         cudaFuncAttributeMaxDynamicSharedMemorySize, SMEM_BYTES);

    mg_init<<<1, 128>>>();
    mogrifier_main<<<GRID_BLOCKS, NT, SMEM_BYTES>>>(x, QL, QR, RL, RR,
                                                    Wih, Whh, bih, bhh,
                                                    (float*)d_out);
}

// round 17
// speedup vs baseline: 1.1387x; 1.0026x over previous
#include <cuda_runtime.h>

// ---------------------------------------------------------------------------
// MogrifierRNN persistent kernel, round 16.  (base = round 15)
//   - gates G2 remap: 8 ogroups x 2 kgroups (kg0: xx@Wih on reused As0,
//     kg1: h@Whh on As1); thread = 1 gate-row x 8 batch-rows
//   - gates W transposed pitch-17 in smem => 1 dense W-wf/kk (was 8 bcasts)
//   - partials to 2 scratch planes; R13 LSTM threads finalize (c stays in regs)
//   - mog G2 / barriers / prefetch ring identical to R15
// ---------------------------------------------------------------------------

#define S_LEN 512
#define B_DIM 128
#define HID   512
#define K_RANK 256
#define NQP   2

#define GRID_BLOCKS 128
#define NT          512
#define APITCH      516                 // floats; 129 f4 per row
#define ABUF        (32 * APITCH)       // 16512 floats
#define WSLOT_F     544                 // slot: 8 rows x 17 f4 (pitch-17)
#define WWARP_F     (2 * WSLOT_F)       // 1088 floats per warp
#define WRING_F     (16 * WWARP_F)      // 17408 floats
#define SCRATCH_F   4608                // mog scr (512*9) >= gates 2*2112
#define SMEM_FLOATS (2 * ABUF + WRING_F + SCRATCH_F)   // 55040
#define SMEM_BYTES  (SMEM_FLOATS * 4)                  // 220,160 B
#define SCRB_OFF    2112                // gates plane B offset (64*33)
#define BAR_STRIDE  32

typedef unsigned long long u64;

// ------------------------- device scratch ----------------------------------
__device__ float g_Q[NQP * HID * HID];   // Q[i][m][n]
__device__ float g_R[NQP * HID * HID];   // R[i][n][m]
__device__ float g_xx[B_DIM * HID];
__device__ float g_h[2][B_DIM * HID];
__device__ unsigned int g_arrive[GRID_BLOCKS * BAR_STRIDE];
__device__ unsigned int g_go_full;

__global__ void mg_init() {
    int i = (int)threadIdx.x;
    if (i < GRID_BLOCKS) g_arrive[i * BAR_STRIDE] = 0u;
    if (i == 0) g_go_full = 0u;
}

__device__ __forceinline__ float sigf(float v) {
    return 1.0f / (1.0f + __expf(-v));
}

// ---- packed fp32x2 FMA ------------------------------------------------------
union F4 { float4 f; ulonglong2 d; };

__device__ __forceinline__ void ffma2(u64& acc, u64 a, u64 b) {
    asm("fma.rn.f32x2 %0, %1, %2, %0;" : "+l"(acc) : "l"(a), "l"(b));
}
__device__ __forceinline__ float pairsum(u64 p) {
    return __uint_as_float((unsigned)p) + __uint_as_float((unsigned)(p >> 32));
}

// ---- cp.async ---------------------------------------------------------------
__device__ __forceinline__ void cpa16(float* dst_smem, const float* src) {
    unsigned d = (unsigned)__cvta_generic_to_shared(dst_smem);
    asm volatile("cp.async.cg.shared.global [%0], [%1], 16;"
                 :: "r"(d), "l"(src) : "memory");
}
__device__ __forceinline__ void cp_commit() {
    asm volatile("cp.async.commit_group;" ::: "memory");
}
template <int N> __device__ __forceinline__ void cp_waitg() {
    asm volatile("cp.async.wait_group %0;" :: "n"(N) : "memory");
}

// ---- barriers ---------------------------------------------------------------
__device__ __forceinline__ unsigned int ld_acq(const unsigned int* p) {
    unsigned int v;
    asm volatile("ld.acquire.gpu.global.u32 %0, [%1];"
                 : "=r"(v) : "l"(p) : "memory");
    return v;
}
__device__ __forceinline__ void st_rel(unsigned int* p, unsigned int v) {
    asm volatile("st.release.gpu.global.u32 [%0], %1;"
                 :: "l"(p), "r"(v) : "memory");
}
__device__ __forceinline__ void bar_named(int id, int cnt) {
    asm volatile("bar.sync %0, %1;" :: "r"(id), "r"(cnt) : "memory");
}

// Row-group barrier: the 32 blocks sharing rt (= blockIdx.x & 3). Direct-poll.
__device__ __forceinline__ void row_barrier(unsigned int& epoch, int rt) {
    epoch++;
    __syncthreads();
    if (threadIdx.x == 0) st_rel(&g_arrive[blockIdx.x * BAR_STRIDE], epoch);
    if (threadIdx.x < 32) {
        while (ld_acq(&g_arrive[(rt + 4 * threadIdx.x) * BAR_STRIDE]) < epoch) { }
    }
    __syncthreads();
}

// Full-grid barrier (once, after precompute).
__device__ __forceinline__ void full_barrier(unsigned int& epoch) {
    epoch++;
    __syncthreads();
    if (blockIdx.x == 0) {
        if (threadIdx.x == 0) st_rel(&g_arrive[0], epoch);
        if (threadIdx.x < GRID_BLOCKS) {
            while (ld_acq(&g_arrive[threadIdx.x * BAR_STRIDE]) < epoch) { }
        }
        __syncthreads();
        if (threadIdx.x == 0) st_rel(&g_go_full, epoch);
    } else {
        if (threadIdx.x == 0) {
            st_rel(&g_arrive[blockIdx.x * BAR_STRIDE], epoch);
            while (ld_acq(&g_go_full) < epoch) { }
        }
        __syncthreads();
    }
}

// ---- staging ----------------------------------------------------------------
// Mog W prefetch: this warp's 8 cols x 16 f4 (own 64-k slice), transposed
// into [col*17 + kk] f4 (pitch-17 => dense conflict-free reads).
__device__ __forceinline__ void mogw_issue(float* myW, const float* W,
                                           int jbase8, int q, int lane) {
#pragma unroll
    for (int i = 0; i < 4; i++) {
        int f = lane + 32 * i;           // 0..127
        int col = f >> 4, kk = f & 15;
        cpa16(myW + (col * 17 + kk) * 4,
              W + (jbase8 + col) * HID + q * 64 + kk * 4);
    }
    cp_commit();
}

// Gates W chunk (G2): this warp's 8 gate-rows (orow = og*8+cl) x 64 k,
// transposed into [cl*17 + kk] f4. One group.
__device__ __forceinline__ void gw_issue(float* slot, const float* Wsrc,
                                         int j0, int og, int kc, int lane) {
#pragma unroll
    for (int i = 0; i < 4; i++) {
        int f = lane + 32 * i;           // 0..127
        int cl = f >> 4, kk = f & 15;
        int orow = og * 8 + cl;
        int gate = orow >> 4, col = orow & 15;
        cpa16(slot + (cl * 17 + kk) * 4,
              Wsrc + (gate * HID + j0 + col) * HID + kc + kk * 4);
    }
    cp_commit();
}

// Mog G2 phase: Dst[b,j] = 2*sig( A[b,:] . W[j,:] ) * Mul[b,j]
// 16 warps = 2 colgroups(cg) x 8 kgroups(q). thread = 1 col x 8 rows.
__device__ __forceinline__ void mog_g2(float* As, const float* myW, float* scr,
                                       const float* Aglob, const float* Mul,
                                       float* Dst, int r0, int j0,
                                       int q, int qtid, int rs, int gc,
                                       int colL) {
    // stage this group's A slice: 32 rows x k[64q, 64q+64)
#pragma unroll
    for (int i = 0; i < 8; i++) {
        int e = qtid + 64 * i;           // 0..511 f4
        int row = e >> 4, kk = e & 15;
        cpa16(As + row * APITCH + q * 64 + kk * 4,
              Aglob + (r0 + row) * HID + q * 64 + kk * 4);
    }
    cp_commit();

    // finalizing group prefetches multiplicands (hides L2 latency)
    float mul[8];
    if (q == 0) {
#pragma unroll
        for (int i = 0; i < 8; i++)
            mul[i] = __ldcs(Mul + (r0 + 4 * i + rs) * HID + j0 + colL);
    }

    cp_waitg<0>();                       // own W + own A slice
    bar_named(1 + q, 64);                // group's slice fully staged

    u64 acc[8];
#pragma unroll
    for (int i = 0; i < 8; i++) acc[i] = 0ull;

    const float4* A4 = reinterpret_cast<const float4*>(As) + rs * 129 + q * 16;
    const float4* W4 = reinterpret_cast<const float4*>(myW) + gc * 17;
#pragma unroll 4
    for (int kk = 0; kk < 16; kk++) {
        F4 w; w.f = W4[kk];
        F4 a0, a1, a2, a3, a4, a5, a6, a7;
        a0.f = A4[0 * 516 + kk];
        a1.f = A4[1 * 516 + kk];
        a2.f = A4[2 * 516 + kk];
        a3.f = A4[3 * 516 + kk];
        a4.f = A4[4 * 516 + kk];
        a5.f = A4[5 * 516 + kk];
        a6.f = A4[6 * 516 + kk];
        a7.f = A4[7 * 516 + kk];
        ffma2(acc[0], a0.d.x, w.d.x); ffma2(acc[1], a1.d.x, w.d.x);
        ffma2(acc[2], a2.d.x, w.d.x); ffma2(acc[3], a3.d.x, w.d.x);
        ffma2(acc[4], a4.d.x, w.d.x); ffma2(acc[5], a5.d.x, w.d.x);
        ffma2(acc[6], a6.d.x, w.d.x); ffma2(acc[7], a7.d.x, w.d.x);
        ffma2(acc[0], a0.d.y, w.d.y); ffma2(acc[1], a1.d.y, w.d.y);
        ffma2(acc[2], a2.d.y, w.d.y); ffma2(acc[3], a3.d.y, w.d.y);
        ffma2(acc[4], a4.d.y, w.d.y); ffma2(acc[5], a5.d.y, w.d.y);
        ffma2(acc[6], a6.d.y, w.d.y); ffma2(acc[7], a7.d.y, w.d.y);
    }

    float p[8];
#pragma unroll
    for (int i = 0; i < 8; i++) p[i] = pairsum(acc[i]);

    if (q != 0) {
#pragma unroll
        for (int i = 0; i < 8; i++) {
            int o = (4 * i + rs) * 16 + colL;
            scr[o * 9 + q] = p[i];
        }
    }
    __syncthreads();
    if (q == 0) {
#pragma unroll
        for (int i = 0; i < 8; i++) {
            int o = (4 * i + rs) * 16 + colL;
            float s = p[i];
#pragma unroll
            for (int qq = 1; qq < 8; qq++) s += scr[o * 9 + qq];
            float v = 2.0f * sigf(s) * mul[i];
            __stcg(Dst + (r0 + 4 * i + rs) * HID + j0 + colL, v);
        }
    }
}

// One-time precompute of Q = QL@QR, R = RL@RR; zero h0.
__device__ void precompute(const float* QL, const float* QR,
                           const float* RL, const float* RR) {
    const int tid = (int)blockIdx.x * NT + (int)threadIdx.x;
    const int stride = GRID_BLOCKS * NT;
    for (int e = tid; e < NQP * HID * HID; e += stride) {
        int i = e >> 18;
        int rem = e & ((1 << 18) - 1);
        int m = rem >> 9, n = rem & 511;
        const float* L  = QL + i * HID * K_RANK + m * K_RANK;
        const float* Rp = QR + i * K_RANK * HID + n;
        float acc = 0.f;
#pragma unroll 8
        for (int k = 0; k < K_RANK; k++) acc = fmaf(L[k], Rp[k * HID], acc);
        g_Q[e] = acc;
    }
    for (int e = tid; e < NQP * HID * HID; e += stride) {
        int i = e >> 18;
        int rem = e & ((1 << 18) - 1);
        int n = rem >> 9, m = rem & 511;
        const float* L  = RL + i * HID * K_RANK + n * K_RANK;
        const float* Rp = RR + i * K_RANK * HID + m;
        float acc = 0.f;
#pragma unroll 8
        for (int k = 0; k < K_RANK; k++) acc = fmaf(L[k], Rp[k * HID], acc);
        g_R[e] = acc;
    }
    for (int e = tid; e < B_DIM * HID; e += stride) {
        g_h[0][e] = 0.f;
    }
}

extern "C" __global__ void __launch_bounds__(NT, 1)
mogrifier_main(const float* __restrict__ x,
               const float* __restrict__ QL, const float* __restrict__ QR,
               const float* __restrict__ RL, const float* __restrict__ RR,
               const float* __restrict__ Wih, const float* __restrict__ Whh,
               const float* __restrict__ bih, const float* __restrict__ bhh,
               float* __restrict__ out) {
    extern __shared__ float smem[];
    float* As0     = smem;               // xx / mog tile (persists into gates)
    float* As1     = smem + ABUF;        // h tile (gates, kgroup1)
    float* Wring   = smem + 2 * ABUF;
    float* scr     = smem + 2 * ABUF + WRING_F;

    const int tid  = (int)threadIdx.x;
    const int lane = tid & 31, wpid = tid >> 5;     // 16 warps
    const int rt = blockIdx.x & 3, ct = (int)blockIdx.x >> 2;
    const int r0 = rt * 32, j0 = ct * 16;
    float* myW = Wring + wpid * WWARP_F;
    unsigned int epoch = 0;

    // ---- mog G2 indices: 2 colgroups x 8 kgroups ----
    const int q  = wpid >> 1;                        // kgroup 0..7
    const int cg = wpid & 1;                         // colgroup 0/1
    const int qtid = (cg << 5) | lane;               // 0..63 within kgroup
    const int rs = lane >> 3;                        // rowslot 0..3
    const int gc = lane & 7;                         // col within 8
    const int jbase8 = j0 + 8 * cg;
    const int colL = 8 * cg + gc;                    // 0..15

    // ---- gates G2 indices: 8 ogroups x 2 kgroups ----
    const int gg = wpid >> 3;                        // gates kgroup 0/1
    const int og = wpid & 7;                         // ogroup 0..7
    const int gtid = tid & 255;
    const int wloc = wpid & 7;                       // finalize colpair (gg0)
    const int jA = j0 + 2 * wloc, jB = jA + 1;

    precompute(QL, QR, RL, RR);

    const float bs0 = bih[jA]        + bhh[jA];
    const float bs1 = bih[512 + jA]  + bhh[512 + jA];
    const float bs2 = bih[1024 + jA] + bhh[1024 + jA];
    const float bs3 = bih[1536 + jA] + bhh[1536 + jA];
    const float bt0 = bih[jB]        + bhh[jB];
    const float bt1 = bih[512 + jB]  + bhh[512 + jB];
    const float bt2 = bih[1024 + jB] + bhh[1024 + jB];
    const float bt3 = bih[1536 + jB] + bhh[1536 + jB];

    const float* Q0 = g_Q;
    const float* Q1 = g_Q + HID * HID;
    const float* R0 = g_R;
    const float* R1 = g_R + HID * HID;

    const int b = r0 + lane;
    const int idxA = b * HID + jA, idxB = b * HID + jB;

    float cA = 0.f, cB = 0.f;            // cell state, registers (gg0 threads)

    full_barrier(epoch);                      // Q/R ready everywhere
    mogw_issue(myW, Q0, jbase8, q, lane);     // prefetch P1 W

    float* tail = out + (size_t)S_LEN * B_DIM * HID;

    for (int t = 0; t < S_LEN; t++) {
        float* hc = g_h[t & 1];
        float* hn = g_h[(t + 1) & 1];
        const float* xt = x + (size_t)t * B_DIM * HID;

        // P1: xx = 2*sig(h @ Q0^T) * x[t]
        mog_g2(As0, myW, scr, hc, xt, g_xx, r0, j0, q, qtid, rs, gc, colL);
        mogw_issue(myW, R0, jbase8, q, lane);
        row_barrier(epoch, rt);

        // P2: h = 2*sig(xx @ R0^T) * h
        mog_g2(As0, myW, scr, g_xx, hc, hc, r0, j0, q, qtid, rs, gc, colL);
        mogw_issue(myW, Q1, jbase8, q, lane);
        row_barrier(epoch, rt);

        // P3: xx = 2*sig(h @ Q1^T) * xx
        mog_g2(As0, myW, scr, hc, g_xx, g_xx, r0, j0, q, qtid, rs, gc, colL);
        mogw_issue(myW, R1, jbase8, q, lane);
        row_barrier(epoch, rt);

        // P4: h = 2*sig(xx @ R1^T) * h   (stages As0 with post-P3 xx)
        mog_g2(As0, myW, scr, g_xx, hc, hc, r0, j0, q, qtid, rs, gc, colL);
        {   // prefetch gates W chunks 0,1 (own source) before the barrier
            const float* Wsrc = gg ? Whh : Wih;
            gw_issue(myW,           Wsrc, j0, og, 0,  lane);
            gw_issue(myW + WSLOT_F, Wsrc, j0, og, 64, lane);
        }
        row_barrier(epoch, rt);

        // P5: gates G2. kg0: xx@Wih on As0 (reused); kg1: h@Whh on As1.
        {
            if (gg) {   // kgroup1 stages the full h tile into As1
#pragma unroll
                for (int i = 0; i < 16; i++) {
                    int e = gtid + 256 * i;
                    int row = e >> 7, qd = e & 127;
                    cpa16(As1 + row * APITCH + qd * 4,
                          hc + (r0 + row) * HID + qd * 4);
                }
                cp_commit();
            }
            const float* Wsrc  = gg ? Whh : Wih;
            const float* Atile = gg ? As1 : As0;

            u64 acc[8];
#pragma unroll
            for (int s = 0; s < 8; s++) acc[s] = 0ull;

            const float4* Abase =
                reinterpret_cast<const float4*>(Atile) + rs * 129;

#pragma unroll 1
            for (int c = 0; c < 8; c++) {
                if (c == 0) { if (gg) cp_waitg<0>(); else cp_waitg<1>(); }
                else if (c == 7) cp_waitg<0>();
                else cp_waitg<1>();
                __syncwarp();
                if (c == 0 && gg) bar_named(10, 256);   // As1 fully staged
                const float4* A4 = Abase + c * 16;
                const float4* W4 =
                    reinterpret_cast<const float4*>(myW + (c & 1) * WSLOT_F)
                    + gc * 17;
#pragma unroll 4
                for (int kk = 0; kk < 16; kk++) {
                    F4 w; w.f = W4[kk];
                    F4 a0, a1, a2, a3, a4, a5, a6, a7;
                    a0.f = A4[0 * 516 + kk];
                    a1.f = A4[1 * 516 + kk];
                    a2.f = A4[2 * 516 + kk];
                    a3.f = A4[3 * 516 + kk];
                    a4.f = A4[4 * 516 + kk];
                    a5.f = A4[5 * 516 + kk];
                    a6.f = A4[6 * 516 + kk];
                    a7.f = A4[7 * 516 + kk];
                    ffma2(acc[0], a0.d.x, w.d.x); ffma2(acc[1], a1.d.x, w.d.x);
                    ffma2(acc[2], a2.d.x, w.d.x); ffma2(acc[3], a3.d.x, w.d.x);
                    ffma2(acc[4], a4.d.x, w.d.x); ffma2(acc[5], a5.d.x, w.d.x);
                    ffma2(acc[6], a6.d.x, w.d.x); ffma2(acc[7], a7.d.x, w.d.x);
                    ffma2(acc[0], a0.d.y, w.d.y); ffma2(acc[1], a1.d.y, w.d.y);
                    ffma2(acc[2], a2.d.y, w.d.y); ffma2(acc[3], a3.d.y, w.d.y);
                    ffma2(acc[4], a4.d.y, w.d.y); ffma2(acc[5], a5.d.y, w.d.y);
                    ffma2(acc[6], a6.d.y, w.d.y); ffma2(acc[7], a7.d.y, w.d.y);
                }
                if (c + 2 < 8)
                    gw_issue(myW + (c & 1) * WSLOT_F, Wsrc, j0, og,
                             (c + 2) * 64, lane);
            }

            // partial store: thread owns orow = og*8+gc, rows 4i+rs
            {
                float* myscr = gg ? (scr + SCRB_OFF) : scr;
                const int orow = og * 8 + gc;
#pragma unroll
                for (int i = 0; i < 8; i++)
                    myscr[orow * 33 + 4 * i + rs] = pairsum(acc[i]);
            }
            __syncthreads();

            if (!gg) {   // warps 0-7: original R13 LSTM mapping (c in regs)
                const int cjA = jA - j0, cjB = jB - j0;
                float pA0 = scr[(0 * 16 + cjA) * 33 + lane]
                          + scr[SCRB_OFF + (0 * 16 + cjA) * 33 + lane] + bs0;
                float pA1 = scr[(1 * 16 + cjA) * 33 + lane]
                          + scr[SCRB_OFF + (1 * 16 + cjA) * 33 + lane] + bs1;
                float pA2 = scr[(2 * 16 + cjA) * 33 + lane]
                          + scr[SCRB_OFF + (2 * 16 + cjA) * 33 + lane] + bs2;
                float pA3 = scr[(3 * 16 + cjA) * 33 + lane]
                          + scr[SCRB_OFF + (3 * 16 + cjA) * 33 + lane] + bs3;
                float pB0 = scr[(0 * 16 + cjB) * 33 + lane]
                          + scr[SCRB_OFF + (0 * 16 + cjB) * 33 + lane] + bt0;
                float pB1 = scr[(1 * 16 + cjB) * 33 + lane]
                          + scr[SCRB_OFF + (1 * 16 + cjB) * 33 + lane] + bt1;
                float pB2 = scr[(2 * 16 + cjB) * 33 + lane]
                          + scr[SCRB_OFF + (2 * 16 + cjB) * 33 + lane] + bt2;
                float pB3 = scr[(3 * 16 + cjB) * 33 + lane]
                          + scr[SCRB_OFF + (3 * 16 + cjB) * 33 + lane] + bt3;

                cA = sigf(pA1) * cA + sigf(pA0) * tanhf(pA2);
                float hAv = sigf(pA3) * tanhf(cA);
                cB = sigf(pB1) * cB + sigf(pB0) * tanhf(pB2);
                float hBv = sigf(pB3) * tanhf(cB);

                __stcg(hn + idxA, hAv);
                __stcg(hn + idxB, hBv);
                float* op = out + (size_t)t * B_DIM * HID;
                op[idxA] = hAv;
                op[idxB] = hBv;
                if (t == S_LEN - 1) {
                    tail[idxA] = hAv;  tail[B_DIM * HID + idxA] = cA;
                    tail[idxB] = hBv;  tail[B_DIM * HID + idxB] = cB;
                }
            }
        }
        mogw_issue(myW, Q0, jbase8, q, lane);   // prefetch next-step P1 W
        row_barrier(epoch, rt);
    }
    cp_waitg<0>();                               // drain dangling prefetch
}

extern "C" void kernel_launch(void* const* d_in, const int* in_sizes, int n_in,
                              void* d_out, int out_size) {
    const float* x   = (const float*)d_in[0];
    const float* QL  = (const float*)d_in[1];
    const float* QR  = (const float*)d_in[2];
    const float* RL  = (const float*)d_in[3];
    const float* RR  = (const float*)d_in[4];
    const float* Wih = (const float*)d_in[5];
    const float* Whh = (const float*)d_in[6];
    const float* bih = (const float*)d_in[7];
    const float* bhh = (const float*)d_in[8];
    (void)in_sizes; (void)n_in; (void)out_size;

    cudaFuncSetAttribute(mogrifier_main,
                         cudaFuncAttributeMaxDynamicSharedMemorySize, SMEM_BYTES);

    mg_init<<<1, 128>>>();
    mogrifier_main<<<GRID_BLOCKS, NT, SMEM_BYTES>>>(x, QL, QR, RL, RR,
                                                    Wih, Whh, bih, bhh,
                                                    (float*)d_out);
}